// round 16
// baseline (speedup 1.0000x reference)
#include <cuda_runtime.h>

#define DD 11
#define DP 12
#define NTOK 49
#define NTOKP 52
#define SEQ 900
#define FFD 64
#define FFP 68
#define NT 512

// ---- packed f32x2 helpers (sm_103a) ----
__device__ __forceinline__ unsigned long long ffma2(unsigned long long a,
                                                    unsigned long long b,
                                                    unsigned long long c) {
    unsigned long long d;
    asm("fma.rn.f32x2 %0, %1, %2, %3;" : "=l"(d) : "l"(a), "l"(b), "l"(c));
    return d;
}
__device__ __forceinline__ unsigned long long add2(unsigned long long a,
                                                   unsigned long long b) {
    unsigned long long d;
    asm("add.rn.f32x2 %0, %1, %2;" : "=l"(d) : "l"(a), "l"(b));
    return d;
}
__device__ __forceinline__ float unpack_add(unsigned long long a) {
    float lo, hi;
    asm("mov.b64 {%0, %1}, %2;" : "=f"(lo), "=f"(hi) : "l"(a));
    return lo + hi;
}

__device__ __forceinline__ float dot12p(const float* __restrict__ a,
                                        const float* __restrict__ b) {
    const ulonglong2* A = (const ulonglong2*)a;
    const ulonglong2* B = (const ulonglong2*)b;
    const ulonglong2 a0 = A[0], a1 = A[1], a2 = A[2];
    const ulonglong2 b0 = B[0], b1 = B[1], b2 = B[2];
    unsigned long long s0 = ffma2(a0.x, b0.x, 0ULL);
    unsigned long long s1 = ffma2(a0.y, b0.y, 0ULL);
    s0 = ffma2(a1.x, b1.x, s0);
    s1 = ffma2(a1.y, b1.y, s1);
    s0 = ffma2(a2.x, b2.x, s0);
    s1 = ffma2(a2.y, b2.y, s1);
    return unpack_add(add2(s0, s1));
}

__device__ __forceinline__ float dot52p(const float* __restrict__ a,
                                        const float* __restrict__ b) {
    const ulonglong2* A = (const ulonglong2*)a;
    const ulonglong2* B = (const ulonglong2*)b;
    unsigned long long s0 = 0ULL, s1 = 0ULL;
    #pragma unroll
    for (int i = 0; i < 13; i++) {
        const ulonglong2 x = A[i], y = B[i];
        s0 = ffma2(x.x, y.x, s0);
        s1 = ffma2(x.y, y.y, s1);
    }
    return unpack_add(add2(s0, s1));
}

__device__ __forceinline__ float dot64p(const float* __restrict__ a,
                                        const float* __restrict__ b) {
    const ulonglong2* A = (const ulonglong2*)a;
    const ulonglong2* B = (const ulonglong2*)b;
    unsigned long long s0 = 0ULL, s1 = 0ULL;
    #pragma unroll
    for (int i = 0; i < 16; i++) {
        const ulonglong2 x = A[i], y = B[i];
        s0 = ffma2(x.x, y.x, s0);
        s1 = ffma2(x.y, y.y, s1);
    }
    return unpack_add(add2(s0, s1));
}

// redundant per-thread row LayerNorm stats: returns (m, rstd) for a 12-float row
// whose pad slot is zero. var = sumsq/11 - m^2 (safe: values O(1), eps guards).
__device__ __forceinline__ void ln_stats(const float* __restrict__ row,
                                         float& m, float& rstd) {
    const ulonglong2* R = (const ulonglong2*)row;
    const ulonglong2 p0 = R[0], p1 = R[1], p2 = R[2];
    unsigned long long s0 = add2(p0.x, p1.x); s0 = add2(s0, p2.x);
    unsigned long long s1 = add2(p0.y, p1.y); s1 = add2(s1, p2.y);
    const float sum = unpack_add(add2(s0, s1));
    unsigned long long q0 = ffma2(p0.x, p0.x, 0ULL);
    unsigned long long q1 = ffma2(p0.y, p0.y, 0ULL);
    q0 = ffma2(p1.x, p1.x, q0); q1 = ffma2(p1.y, p1.y, q1);
    q0 = ffma2(p2.x, p2.x, q0); q1 = ffma2(p2.y, p2.y, q1);
    const float ss = unpack_add(add2(q0, q1));
    m = sum * (1.f / 11.f);
    const float var = ss * (1.f / 11.f) - m * m;
    rstd = rsqrtf(var + 1e-5f);
}

__global__ __launch_bounds__(NT, 3) void pve_kernel(
    const float* __restrict__ x,     // [10,16,16]
    const float* __restrict__ Wqkv,  // [33,11]
    const float* __restrict__ Wo,    // [11,11]
    const float* __restrict__ W1,    // [64,11]
    const float* __restrict__ W2,    // [11,64]
    const float* __restrict__ ln1,   // [11]
    const float* __restrict__ ln2,   // [11]
    float* __restrict__ out)         // [256,10,900]
{
    __shared__ __align__(16) float sWqkv[33 * DP];
    __shared__ __align__(16) float sWo[11 * DP];
    __shared__ __align__(16) float sW1[FFD * DP];
    __shared__ __align__(16) float sW2[11 * FFP];
    __shared__ float sLn1[DD], sLn2[DD];
    __shared__ __align__(16) float sX[50 * DP];
    __shared__ __align__(16) float sQ[50 * DP];
    __shared__ __align__(16) float sK[50 * DP];
    __shared__ __align__(16) float sVt[DD * NTOKP];
    __shared__ __align__(16) float sE[50 * NTOKP];
    __shared__ __align__(16) float sA[50 * DP];
    __shared__ __align__(16) float sR[50 * DP];
    __shared__ __align__(16) float sX1[50 * DP];
    __shared__ __align__(16) float sH[50 * FFP];
    __shared__ __align__(16) float sO[50 * DP];
    __shared__ float sZinv[50];

    const int tid = threadIdx.x;
    const int b  = blockIdx.x;
    const int ph = b >> 4;
    const int pw = b & 15;

    // ================= A: stage weights (padded) + tokens + pads =================
    for (int i = tid; i < 33 * DP; i += NT) {
        const int r = i / DP, e = i - r * DP;
        sWqkv[i] = (e < DD) ? Wqkv[r * DD + e] : 0.f;
    }
    for (int i = tid; i < 11 * DP; i += NT) {
        const int r = i / DP, e = i - r * DP;
        sWo[i] = (e < DD) ? Wo[r * DD + e] : 0.f;
    }
    for (int i = tid; i < FFD * DP; i += NT) {
        const int r = i / DP, e = i - r * DP;
        sW1[i] = (e < DD) ? W1[r * DD + e] : 0.f;
    }
    for (int i = tid; i < 11 * FFP; i += NT) {
        const int r = i / FFP, k = i - r * FFP;
        if (k < FFD) sW2[i] = W2[r * FFD + k];
    }
    if (tid < DD) { sLn1[tid] = ln1[tid]; sLn2[tid] = ln2[tid]; }
    for (int idx = tid; idx < 50 * DP; idx += NT) {     // token inputs; row 49 = zero
        const int t = idx / DP, c = idx - t * DP;
        float v = 0.f;
        if (t < NTOK && c < DD) {
            const int i = t / 7, j = t - i * 7;
            const int hh = ph + i - 3, ww = pw + j - 3;
            const bool inb = ((unsigned)hh < 16u) && ((unsigned)ww < 16u);
            if (c < 10) v = inb ? x[c * 256 + hh * 16 + ww] : 0.f;
            else        v = inb ? 0.f : 1.f;
        }
        sX[idx] = v;
    }
    for (int t = tid; t < 50; t += NT) {                // pad slots (stay 0 forever)
        sQ[t * DP + DD] = 0.f; sK[t * DP + DD] = 0.f;
        sA[t * DP + DD] = 0.f; sR[t * DP + DD] = 0.f;
    }
    for (int i = tid; i < DD * 3; i += NT) {            // sVt tails u=49..51
        const int d = i / 3;
        sVt[d * NTOKP + NTOK + (i - d * 3)] = 0.f;
    }
    __syncthreads();

    // ================= B: QKV, untiled (1650 dot12) ==============================
    {
        const float scale = rsqrtf(11.f);
        for (int idx = tid; idx < 50 * 33; idx += NT) {
            const int row = idx / 33, col = idx - row * 33;
            const float a = dot12p(&sX[row * DP], &sWqkv[col * DP]);
            const int p = col / DD, d = col - p * DD;
            if (p == 0)      sQ[row * DP + d] = a * scale;
            else if (p == 1) sK[row * DP + d] = a;
            else if (row < NTOK) sVt[d * NTOKP + row] = a;
        }
    }
    __syncthreads();

    // ================= C: E = exp(QK^T), untiled (50x52 incl pads) ===============
    for (int idx = tid; idx < 50 * NTOKP; idx += NT) {
        const int r = idx / NTOKP, u = idx - r * NTOKP;
        sE[idx] = (u < NTOK) ? __expf(dot12p(&sQ[r * DP], &sK[u * DP])) : 0.f;
    }
    __syncthreads();

    // ================= D: A = E @ V^T (550 dot52) + Z (50) =======================
    for (int idx = tid; idx < 600; idx += NT) {
        if (idx < 550) {
            const int r = idx / DD, d = idx - r * DD;
            sA[r * DP + d] = dot52p(&sE[r * NTOKP], &sVt[d * NTOKP]);
        } else {
            const int r = idx - 550;
            const ulonglong2* E = (const ulonglong2*)&sE[r * NTOKP];
            unsigned long long z0 = 0ULL, z1 = 0ULL;
            #pragma unroll
            for (int i = 0; i < 13; i++) {
                const ulonglong2 e = E[i];
                z0 = add2(z0, e.x);
                z1 = add2(z1, e.y);
            }
            sZinv[r] = 1.f / (851.f + unpack_add(add2(z0, z1)));
        }
    }
    __syncthreads();

    // ================= E: Wo proj + residual (550 dot12) =========================
    for (int idx = tid; idx < 550; idx += NT) {
        const int r = idx / DD, d = idx - r * DD;
        sR[r * DP + d] = sX[r * DP + d] + dot12p(&sWo[d * DP], &sA[r * DP]) * sZinv[r];
    }
    __syncthreads();

    // ================= LN1: 600 items, redundant row stats =======================
    for (int idx = tid; idx < 600; idx += NT) {
        const int r = idx / DP, d = idx - r * DP;
        float m, rstd;
        ln_stats(&sR[r * DP], m, rstd);
        sX1[idx] = (d < DD) ? (sR[idx] - m) * rstd * sLn1[d] : 0.f;
    }
    __syncthreads();

    // ================= F: FF1 + relu, untiled (3200 dot12) =======================
    for (int idx = tid; idx < 50 * FFD; idx += NT) {
        const int r = idx >> 6, f = idx & 63;
        sH[r * FFP + f] = fmaxf(dot12p(&sW1[f * DP], &sX1[r * DP]), 0.f);
    }
    __syncthreads();

    // ================= G: FF2 + residual (550 dot64) =============================
    for (int idx = tid; idx < 550; idx += NT) {
        const int r = idx / DD, d = idx - r * DD;
        sR[r * DP + d] = sX1[r * DP + d] + dot64p(&sH[r * FFP], &sW2[d * FFP]);
    }
    __syncthreads();

    // ================= LN2: 600 items -> sO ======================================
    for (int idx = tid; idx < 600; idx += NT) {
        const int r = idx / DP, d = idx - r * DP;
        float m, rstd;
        ln_stats(&sR[r * DP], m, rstd);
        sO[idx] = (d < DD) ? (sR[idx] - m) * rstd * sLn2[d] : 0.f;
    }
    __syncthreads();

    // ================= H: output (broadcast fill + window overwrite) =============
    float* ob = out + b * (10 * SEQ);
    for (int idx = tid; idx < 10 * (SEQ / 4); idx += NT) {
        const int c = idx / (SEQ / 4), q = idx - c * (SEQ / 4);
        const float z = sO[NTOK * DP + c];
        ((float4*)(ob + c * SEQ))[q] = make_float4(z, z, z, z);
    }
    __syncthreads();
    for (int idx = tid; idx < 10 * NTOK; idx += NT) {
        const int c = idx / NTOK, w = idx - c * NTOK;
        const int i = w / 7, j = w - i * 7;
        ob[c * SEQ + i * 30 + j] = sO[w * DP + c];
    }
}

extern "C" void kernel_launch(void* const* d_in, const int* in_sizes, int n_in,
                              void* d_out, int out_size) {
    const float* x    = (const float*)d_in[0];
    const float* Wqkv = (const float*)d_in[1];
    const float* Wo   = (const float*)d_in[2];
    const float* W1   = (const float*)d_in[3];
    const float* W2   = (const float*)d_in[4];
    const float* ln1  = (const float*)d_in[5];
    const float* ln2  = (const float*)d_in[6];
    float* out = (float*)d_out;
    pve_kernel<<<256, NT>>>(x, Wqkv, Wo, W1, W2, ln1, ln2, out);
}

// round 17
// speedup vs baseline: 1.0311x; 1.0311x over previous
#include <cuda_runtime.h>

#define DD 11
#define DP 12
#define NTOK 49
#define NTOKP 52
#define SEQ 900
#define FFD 64
#define FFP 68
#define NT 512
#define NW 16

// ---- packed f32x2 helpers (sm_103a) ----
__device__ __forceinline__ unsigned long long ffma2(unsigned long long a,
                                                    unsigned long long b,
                                                    unsigned long long c) {
    unsigned long long d;
    asm("fma.rn.f32x2 %0, %1, %2, %3;" : "=l"(d) : "l"(a), "l"(b), "l"(c));
    return d;
}
__device__ __forceinline__ unsigned long long add2(unsigned long long a,
                                                   unsigned long long b) {
    unsigned long long d;
    asm("add.rn.f32x2 %0, %1, %2;" : "=l"(d) : "l"(a), "l"(b));
    return d;
}
__device__ __forceinline__ float unpack_add(unsigned long long a) {
    float lo, hi;
    asm("mov.b64 {%0, %1}, %2;" : "=f"(lo), "=f"(hi) : "l"(a));
    return lo + hi;
}

// dot of preloaded 12-float vector (a0..a2) against shared vector b
__device__ __forceinline__ float dot12r(ulonglong2 a0, ulonglong2 a1, ulonglong2 a2,
                                        ulonglong2 b0, ulonglong2 b1, ulonglong2 b2) {
    unsigned long long s0 = ffma2(a0.x, b0.x, 0ULL);
    unsigned long long s1 = ffma2(a0.y, b0.y, 0ULL);
    s0 = ffma2(a1.x, b1.x, s0);
    s1 = ffma2(a1.y, b1.y, s1);
    s0 = ffma2(a2.x, b2.x, s0);
    s1 = ffma2(a2.y, b2.y, s1);
    return unpack_add(add2(s0, s1));
}

__device__ __forceinline__ float dot12p(const float* __restrict__ a,
                                        const float* __restrict__ b) {
    const ulonglong2* A = (const ulonglong2*)a;
    const ulonglong2* B = (const ulonglong2*)b;
    return dot12r(A[0], A[1], A[2], B[0], B[1], B[2]);
}

__device__ __forceinline__ float dot52p(const float* __restrict__ a,
                                        const float* __restrict__ b) {
    const ulonglong2* A = (const ulonglong2*)a;
    const ulonglong2* B = (const ulonglong2*)b;
    unsigned long long s0 = 0ULL, s1 = 0ULL;
    #pragma unroll
    for (int i = 0; i < 13; i++) {
        const ulonglong2 x = A[i], y = B[i];
        s0 = ffma2(x.x, y.x, s0);
        s1 = ffma2(x.y, y.y, s1);
    }
    return unpack_add(add2(s0, s1));
}

__device__ __forceinline__ float dot64p(const float* __restrict__ a,
                                        const float* __restrict__ b) {
    const ulonglong2* A = (const ulonglong2*)a;
    const ulonglong2* B = (const ulonglong2*)b;
    unsigned long long s0 = 0ULL, s1 = 0ULL;
    #pragma unroll
    for (int i = 0; i < 16; i++) {
        const ulonglong2 x = A[i], y = B[i];
        s0 = ffma2(x.x, y.x, s0);
        s1 = ffma2(x.y, y.y, s1);
    }
    return unpack_add(add2(s0, s1));
}

// redundant per-thread row LayerNorm stats over a 12-float row (pad slot zero)
__device__ __forceinline__ void ln_stats(const float* __restrict__ row,
                                         float& m, float& rstd) {
    const ulonglong2* R = (const ulonglong2*)row;
    const ulonglong2 p0 = R[0], p1 = R[1], p2 = R[2];
    unsigned long long s0 = add2(p0.x, p1.x); s0 = add2(s0, p2.x);
    unsigned long long s1 = add2(p0.y, p1.y); s1 = add2(s1, p2.y);
    const float sum = unpack_add(add2(s0, s1));
    unsigned long long q0 = ffma2(p0.x, p0.x, 0ULL);
    unsigned long long q1 = ffma2(p0.y, p0.y, 0ULL);
    q0 = ffma2(p1.x, p1.x, q0); q1 = ffma2(p1.y, p1.y, q1);
    q0 = ffma2(p2.x, p2.x, q0); q1 = ffma2(p2.y, p2.y, q1);
    const float ss = unpack_add(add2(q0, q1));
    m = sum * (1.f / 11.f);
    const float var = ss * (1.f / 11.f) - m * m;
    rstd = rsqrtf(var + 1e-5f);
}

__global__ __launch_bounds__(NT, 2) void pve_kernel(
    const float* __restrict__ x,     // [10,16,16]
    const float* __restrict__ Wqkv,  // [33,11]
    const float* __restrict__ Wo,    // [11,11]
    const float* __restrict__ W1,    // [64,11]
    const float* __restrict__ W2,    // [11,64]
    const float* __restrict__ ln1,   // [11]
    const float* __restrict__ ln2,   // [11]
    float* __restrict__ out)         // [256,10,900]
{
    __shared__ __align__(16) float sWqkv[33 * DP];
    __shared__ __align__(16) float sWo[11 * DP];
    __shared__ __align__(16) float sW1[FFD * DP];
    __shared__ __align__(16) float sW2[11 * FFP];
    __shared__ float sLn1[DD], sLn2[DD];
    __shared__ __align__(16) float sX[50 * DP];
    __shared__ __align__(16) float sQ[50 * DP];
    __shared__ __align__(16) float sK[50 * DP];
    __shared__ __align__(16) float sVt[DD * NTOKP];
    __shared__ __align__(16) float sE[50 * NTOKP];
    __shared__ __align__(16) float sA[50 * DP];
    __shared__ __align__(16) float sR[50 * DP];
    __shared__ __align__(16) float sX1[50 * DP];
    __shared__ __align__(16) float sH[50 * FFP];
    __shared__ __align__(16) float sO[50 * DP];
    __shared__ float sZinv[50];

    const int tid  = threadIdx.x;
    const int wid  = tid >> 5;
    const int lane = tid & 31;
    const int b  = blockIdx.x;
    const int ph = b >> 4;
    const int pw = b & 15;

    // ================= A: stage weights (padded) + tokens + pads =================
    for (int i = tid; i < 33 * DP; i += NT) {
        const int r = i / DP, e = i - r * DP;
        sWqkv[i] = (e < DD) ? Wqkv[r * DD + e] : 0.f;
    }
    for (int i = tid; i < 11 * DP; i += NT) {
        const int r = i / DP, e = i - r * DP;
        sWo[i] = (e < DD) ? Wo[r * DD + e] : 0.f;
    }
    for (int i = tid; i < FFD * DP; i += NT) {
        const int r = i / DP, e = i - r * DP;
        sW1[i] = (e < DD) ? W1[r * DD + e] : 0.f;
    }
    for (int i = tid; i < 11 * FFP; i += NT) {
        const int r = i / FFP, k = i - r * FFP;
        if (k < FFD) sW2[i] = W2[r * FFD + k];
    }
    if (tid < DD) { sLn1[tid] = ln1[tid]; sLn2[tid] = ln2[tid]; }
    for (int idx = tid; idx < 50 * DP; idx += NT) {     // token inputs; row 49 = zero
        const int t = idx / DP, c = idx - t * DP;
        float v = 0.f;
        if (t < NTOK && c < DD) {
            const int i = t / 7, j = t - i * 7;
            const int hh = ph + i - 3, ww = pw + j - 3;
            const bool inb = ((unsigned)hh < 16u) && ((unsigned)ww < 16u);
            if (c < 10) v = inb ? x[c * 256 + hh * 16 + ww] : 0.f;
            else        v = inb ? 0.f : 1.f;
        }
        sX[idx] = v;
    }
    for (int t = tid; t < 50; t += NT) {                // pad slots (stay 0 forever)
        sQ[t * DP + DD] = 0.f; sK[t * DP + DD] = 0.f;
        sA[t * DP + DD] = 0.f; sR[t * DP + DD] = 0.f;
    }
    for (int i = tid; i < DD * 3; i += NT) {            // sVt tails u=49..51
        const int d = i / 3;
        sVt[d * NTOKP + NTOK + (i - d * 3)] = 0.f;
    }
    __syncthreads();

    // ========== B: QKV, warp-broadcast (66 warp-items: col x row-block) ==========
    {
        const float scale = rsqrtf(11.f);
        for (int wi = wid; wi < 66; wi += NW) {
            const int c = wi >> 1;                      // 0..32
            const int r = ((wi & 1) << 5) + lane;       // 0..63
            const ulonglong2* W = (const ulonglong2*)&sWqkv[c * DP];
            const ulonglong2 w0 = W[0], w1p = W[1], w2p = W[2];   // broadcast
            if (r < 50) {
                const ulonglong2* X = (const ulonglong2*)&sX[r * DP];
                const float a = dot12r(X[0], X[1], X[2], w0, w1p, w2p);
                if (c < DD)       sQ[r * DP + c] = a * scale;
                else if (c < 22)  sK[r * DP + (c - DD)] = a;
                else if (r < NTOK) sVt[(c - 22) * NTOKP + r] = a;
            }
        }
    }
    __syncthreads();

    // ========== C: E = exp(QK^T), warp-broadcast (100: q-row x key-block) ========
    for (int wi = wid; wi < 100; wi += NW) {
        const int r = wi >> 1;                          // 0..49
        const int u = ((wi & 1) << 5) + lane;           // 0..63
        const ulonglong2* Q = (const ulonglong2*)&sQ[r * DP];
        const ulonglong2 q0 = Q[0], q1 = Q[1], q2 = Q[2];   // broadcast
        if (u < NTOKP) {
            float e = 0.f;
            if (u < NTOK) {
                const ulonglong2* K = (const ulonglong2*)&sK[u * DP];
                e = __expf(dot12r(q0, q1, q2, K[0], K[1], K[2]));
            }
            sE[r * NTOKP + u] = e;
        }
    }
    __syncthreads();

    // ================= D: A = E @ V^T (550 dot52) + Z (50) =======================
    for (int idx = tid; idx < 600; idx += NT) {
        if (idx < 550) {
            const int r = idx / DD, d = idx - r * DD;
            sA[r * DP + d] = dot52p(&sE[r * NTOKP], &sVt[d * NTOKP]);
        } else {
            const int r = idx - 550;
            const ulonglong2* E = (const ulonglong2*)&sE[r * NTOKP];
            unsigned long long z0 = 0ULL, z1 = 0ULL;
            #pragma unroll
            for (int i = 0; i < 13; i++) {
                const ulonglong2 e = E[i];
                z0 = add2(z0, e.x);
                z1 = add2(z1, e.y);
            }
            sZinv[r] = 1.f / (851.f + unpack_add(add2(z0, z1)));
        }
    }
    __syncthreads();

    // ================= E: Wo proj + residual (550 dot12) =========================
    for (int idx = tid; idx < 550; idx += NT) {
        const int r = idx / DD, d = idx - r * DD;
        sR[r * DP + d] = sX[r * DP + d] + dot12p(&sWo[d * DP], &sA[r * DP]) * sZinv[r];
    }
    __syncthreads();

    // ================= LN1: 600 items, redundant row stats =======================
    for (int idx = tid; idx < 600; idx += NT) {
        const int r = idx / DP, d = idx - r * DP;
        float m, rstd;
        ln_stats(&sR[r * DP], m, rstd);
        sX1[idx] = (d < DD) ? (sR[idx] - m) * rstd * sLn1[d] : 0.f;
    }
    __syncthreads();

    // ========== F: FF1 + relu, warp-broadcast (100: row x f-block) ===============
    for (int wi = wid; wi < 100; wi += NW) {
        const int r = wi >> 1;                          // 0..49
        const int f = ((wi & 1) << 5) + lane;           // 0..63, all valid
        const ulonglong2* X = (const ulonglong2*)&sX1[r * DP];
        const ulonglong2 x0 = X[0], x1p = X[1], x2p = X[2];   // broadcast
        const ulonglong2* W = (const ulonglong2*)&sW1[f * DP];
        sH[r * FFP + f] = fmaxf(dot12r(x0, x1p, x2p, W[0], W[1], W[2]), 0.f);
    }
    __syncthreads();

    // ================= G: FF2 + residual (550 dot64) =============================
    for (int idx = tid; idx < 550; idx += NT) {
        const int r = idx / DD, d = idx - r * DD;
        sR[r * DP + d] = sX1[r * DP + d] + dot64p(&sH[r * FFP], &sW2[d * FFP]);
    }
    __syncthreads();

    // ================= LN2: 600 items -> sO ======================================
    for (int idx = tid; idx < 600; idx += NT) {
        const int r = idx / DP, d = idx - r * DP;
        float m, rstd;
        ln_stats(&sR[r * DP], m, rstd);
        sO[idx] = (d < DD) ? (sR[idx] - m) * rstd * sLn2[d] : 0.f;
    }
    __syncthreads();

    // ================= H: output (broadcast fill + window overwrite) =============
    float* ob = out + b * (10 * SEQ);
    for (int idx = tid; idx < 10 * (SEQ / 4); idx += NT) {
        const int c = idx / (SEQ / 4), q = idx - c * (SEQ / 4);
        const float z = sO[NTOK * DP + c];
        ((float4*)(ob + c * SEQ))[q] = make_float4(z, z, z, z);
    }
    __syncthreads();
    for (int idx = tid; idx < 10 * NTOK; idx += NT) {
        const int c = idx / NTOK, w = idx - c * NTOK;
        const int i = w / 7, j = w - i * 7;
        ob[c * SEQ + i * 30 + j] = sO[w * DP + c];
    }
}

extern "C" void kernel_launch(void* const* d_in, const int* in_sizes, int n_in,
                              void* d_out, int out_size) {
    const float* x    = (const float*)d_in[0];
    const float* Wqkv = (const float*)d_in[1];
    const float* Wo   = (const float*)d_in[2];
    const float* W1   = (const float*)d_in[3];
    const float* W2   = (const float*)d_in[4];
    const float* ln1  = (const float*)d_in[5];
    const float* ln2  = (const float*)d_in[6];
    float* out = (float*)d_out;
    pve_kernel<<<256, NT>>>(x, Wqkv, Wo, W1, W2, ln1, ln2, out);
}